// round 15
// baseline (speedup 1.0000x reference)
#include <cuda_runtime.h>
#include <cstdint>

// Problem constants (fixed by reference setup_inputs)
#define NBATCH 16
#define NPTS 131072
#define NCH 6
#define KSEL 1024

#define CTAS_PER_B 16             // CTAs per batch
#define NPAIRS (NBATCH / 2)       // 8 batch pairs
#define NPC (NPTS / CTAS_PER_B)   // 8192 points per CTA per batch
#define THREADS 512
#define PPT (NPC / THREADS)       // 16 points per thread per batch
#define NGROUPS (PPT / 4)         // 4 float4-groups per thread per batch
#define NWARPS (THREADS / 32)     // 16

// Per-CTA publish slots, 32B each, PER (batch, iteration): zeroed by init kernel.
//   [0..1] = b128 A {pk, xy} : pk != 0 -> valid
//   [2..3] = b128 B {z, tag} : tag = 1 -> valid
__device__ unsigned long long g_pub[NBATCH][KSEL][CTAS_PER_B][4];

__global__ void fps_init_kernel() {
    unsigned long long* p = &g_pub[0][0][0][0];
    const int n = NBATCH * KSEL * CTAS_PER_B * 4;
    for (int i = blockIdx.x * blockDim.x + threadIdx.x; i < n;
         i += gridDim.x * blockDim.x)
        p[i] = 0ULL;
}

__device__ __forceinline__ void st_b128_relaxed(unsigned long long* p,
                                                unsigned long long lo,
                                                unsigned long long hi) {
    asm volatile(
        "{ .reg .b128 t; mov.b128 t, {%1, %2}; st.relaxed.gpu.global.b128 [%0], t; }"
        :: "l"(p), "l"(lo), "l"(hi) : "memory");
}
__device__ __forceinline__ void ld_b128_relaxed(unsigned long long& lo,
                                                unsigned long long& hi,
                                                const unsigned long long* p) {
    asm volatile(
        "{ .reg .b128 t; ld.relaxed.gpu.global.b128 t, [%2]; mov.b128 {%0, %1}, t; }"
        : "=l"(lo), "=l"(hi) : "l"(p) : "memory");
}

// ---- packed f32x2 helpers (per-lane IEEE rn, bit-identical to scalar) ----
__device__ __forceinline__ unsigned long long add2(unsigned long long a, unsigned long long b) {
    unsigned long long r;
    asm("add.rn.f32x2 %0, %1, %2;" : "=l"(r) : "l"(a), "l"(b));
    return r;
}
__device__ __forceinline__ unsigned long long mul2(unsigned long long a, unsigned long long b) {
    unsigned long long r;
    asm("mul.rn.f32x2 %0, %1, %2;" : "=l"(r) : "l"(a), "l"(b));
    return r;
}
__device__ __forceinline__ unsigned long long fma2(unsigned long long a, unsigned long long b,
                                                   unsigned long long c) {
    unsigned long long r;
    asm("fma.rn.f32x2 %0, %1, %2, %3;" : "=l"(r) : "l"(a), "l"(b), "l"(c));
    return r;
}
__device__ __forceinline__ void unpack2(float& lo, float& hi, unsigned long long v) {
    asm("mov.b64 {%0, %1}, %2;" : "=f"(lo), "=f"(hi) : "l"(v));
}
__device__ __forceinline__ unsigned long long pack2(float lo, float hi) {
    unsigned long long r;
    asm("mov.b64 %0, {%1, %2};" : "=l"(r) : "f"(lo), "f"(hi));
    return r;
}
__device__ __forceinline__ unsigned long long bcast2(float v) {
    unsigned long long r;
    asm("mov.b64 %0, {%1, %1};" : "=l"(r) : "f"(v));
    return r;
}

// Distance formula (FROZEN, bit-exact vs reference):
//   d = fma(dz,dz, fma(dx,dx, dy*dy)),  dx = x + (-qx) etc.
// Computes one batch's distance pass; returns warp-local packed argmax.
__device__ __forceinline__ unsigned long long compute_phase(
    const ulonglong2* __restrict__ sx2, const ulonglong2* __restrict__ sy2,
    const ulonglong2* __restrict__ sz2, float* dist,
    float qx, float qy, float qz, int tid, int p0) {
    const unsigned long long nqx2 = bcast2(-qx);
    const unsigned long long nqy2 = bcast2(-qy);
    const unsigned long long nqz2 = bcast2(-qz);
    float best = -1.0f;
    unsigned bidx = 0;
#pragma unroll
    for (int g = 0; g < NGROUPS; ++g) {
        const int e = g * THREADS + tid;                 // conflict-free LDS.128
        ulonglong2 X = sx2[e];
        ulonglong2 Y = sy2[e];
        ulonglong2 Z = sz2[e];
        const unsigned gi = (unsigned)(p0 + (e << 2));
        const int j = g * 4;
        {
            unsigned long long dx = add2(X.x, nqx2);
            unsigned long long dy = add2(Y.x, nqy2);
            unsigned long long dz = add2(Z.x, nqz2);
            unsigned long long d2 = fma2(dz, dz, fma2(dx, dx, mul2(dy, dy)));
            float d0, d1; unpack2(d0, d1, d2);
            float n0 = fminf(dist[j + 0], d0); dist[j + 0] = n0;
            if (n0 > best) { best = n0; bidx = gi + 0; }
            float n1 = fminf(dist[j + 1], d1); dist[j + 1] = n1;
            if (n1 > best) { best = n1; bidx = gi + 1; }
        }
        {
            unsigned long long dx = add2(X.y, nqx2);
            unsigned long long dy = add2(Y.y, nqy2);
            unsigned long long dz = add2(Z.y, nqz2);
            unsigned long long d2 = fma2(dz, dz, fma2(dx, dx, mul2(dy, dy)));
            float d0, d1; unpack2(d0, d1, d2);
            float n0 = fminf(dist[j + 2], d0); dist[j + 2] = n0;
            if (n0 > best) { best = n0; bidx = gi + 2; }
            float n1 = fminf(dist[j + 3], d1); dist[j + 3] = n1;
            if (n1 > best) { best = n1; bidx = gi + 3; }
        }
    }
    unsigned long long pk =
        ((unsigned long long)__float_as_uint(best) << 32) |
        (unsigned long long)(~bidx);
#pragma unroll
    for (int off = 16; off > 0; off >>= 1) {
        unsigned long long o = __shfl_down_sync(0xffffffffu, pk, off);
        if (o > pk) pk = o;
    }
    return pk;
}

// warp0 sync phase: CTA-reduce sred, publish our candidate for (bat,it) using
// the PUBLISHED batch's SMEM slice (sx,sy,sz), poll slot (pbat,pit) with an
// aged first round, select winner, write sbc (+hist when record).
__device__ __forceinline__ void sync_phase(
    unsigned long long* sred, unsigned long long* sbc, unsigned int* hist,
    const float* sx, const float* sy, const float* sz,
    int bat, int it, int pbat, int pit, bool do_poll,
    int c, int p0, int lane, bool record) {
    // Aged poll: issue first-round loads BEFORE the reduce so they fly in parallel.
    unsigned long long a0 = 1, a1 = 0, b0 = 0, b1 = 1;
    const unsigned long long* pent = &g_pub[pbat][pit][lane & 15][0];
    if (do_poll && lane < CTAS_PER_B) {
        ld_b128_relaxed(a0, a1, &pent[0]);
        ld_b128_relaxed(b0, b1, &pent[2]);
    }
    // CTA reduce over 16 warp results.
    unsigned long long v = (lane < NWARPS) ? sred[lane] : 0ULL;
#pragma unroll
    for (int off = 8; off > 0; off >>= 1) {
        unsigned long long o = __shfl_xor_sync(0xffffffffu, v, off);
        if (o > v) v = o;
    }
    if (lane == 0) {
        unsigned widxL = ~(unsigned)(v & 0xffffffffULL);
        int local = (int)widxL - p0;                     // winner is in OUR slice
        float wx = sx[local], wy = sy[local], wz = sz[local];
        unsigned long long* ent = &g_pub[bat][it][c][0];
        st_b128_relaxed(&ent[2], pack2(wz, 0.0f), 1ULL); // B {z, tag}
        st_b128_relaxed(&ent[0], v, pack2(wx, wy));      // A {pk, xy}
    }
    if (!do_poll) return;
    unsigned long long pkj = 0, xyj = 0, zj = 0;
    if (lane < CTAS_PER_B) {
        while (a0 == 0ULL || b1 == 0ULL) {               // first round usually hits
            ld_b128_relaxed(a0, a1, &pent[0]);
            ld_b128_relaxed(b0, b1, &pent[2]);
        }
        pkj = a0; xyj = a1; zj = b0;
    }
    unsigned long long m = pkj;
#pragma unroll
    for (int off = 8; off > 0; off >>= 1) {
        unsigned long long o = __shfl_xor_sync(0xffffffffu, m, off);
        if (o > m) m = o;
    }
    unsigned long long m0 = __shfl_sync(0xffffffffu, m, 0);
    unsigned bal = __ballot_sync(0xffffffffu, pkj == m0);
    int win = __ffs(bal) - 1;                            // smallest CTA on tie
    if (lane == win) {
        sbc[0] = xyj;
        sbc[1] = zj;
    }
    if (record && lane == 0) {
        hist[pit] = ~(unsigned)(m0 & 0xffffffffULL);
    }
}

__global__ __launch_bounds__(THREADS, 1)
void fps_kernel(const float* __restrict__ pts, float* __restrict__ out) {
    extern __shared__ float sh[];
    float* sxA = sh;
    float* syA = sh + NPC;
    float* szA = sh + 2 * NPC;
    float* sxB = sh + 3 * NPC;
    float* syB = sh + 4 * NPC;
    float* szB = sh + 5 * NPC;
    __shared__ unsigned long long sred[NWARPS];
    __shared__ unsigned long long sbcA[2], sbcB[2];      // winner broadcast {xy, z}
    __shared__ unsigned int histA[KSEL], histB[KSEL];

    const int tid = threadIdx.x;
    const int p   = blockIdx.x / CTAS_PER_B;             // batch pair
    const int c   = blockIdx.x % CTAS_PER_B;
    const int bA  = 2 * p, bB = 2 * p + 1;
    const float* baseA = pts + (size_t)bA * NPTS * NCH;
    const float* baseB = pts + (size_t)bB * NPTS * NCH;
    const int p0 = c * NPC;

    // Stage both slices into SMEM.
    for (int i = tid; i < NPC; i += THREADS) {
        const float* rA = baseA + (size_t)(p0 + i) * NCH;
        sxA[i] = rA[0]; syA[i] = rA[1]; szA[i] = rA[2];
        const float* rB = baseB + (size_t)(p0 + i) * NCH;
        sxB[i] = rB[0]; syB[i] = rB[1]; szB[i] = rB[2];
    }

    float distA[PPT], distB[PPT];
#pragma unroll
    for (int j = 0; j < PPT; ++j) {
        distA[j] = __int_as_float(0x7f800000);
        distB[j] = __int_as_float(0x7f800000);
    }

    float qxA = baseA[0], qyA = baseA[1], qzA = baseA[2];
    float qxB = baseB[0], qyB = baseB[1], qzB = baseB[2];
    if (c == 0 && tid < NCH) out[(size_t)bA * KSEL * NCH + tid] = baseA[tid];
    if (c == 1 && tid < NCH) out[(size_t)bB * KSEL * NCH + tid] = baseB[tid];
    __syncthreads();

    const int lane = tid & 31;
    const int warp = tid >> 5;

    const ulonglong2* sxA2 = (const ulonglong2*)sxA;
    const ulonglong2* syA2 = (const ulonglong2*)syA;
    const ulonglong2* szA2 = (const ulonglong2*)szA;
    const ulonglong2* sxB2 = (const ulonglong2*)sxB;
    const ulonglong2* syB2 = (const ulonglong2*)syB;
    const ulonglong2* szB2 = (const ulonglong2*)szB;

    for (int it = 1; it < KSEL; ++it) {
        // ---- phase A: compute A(it) with qA(it-1) ----
        unsigned long long pkA =
            compute_phase(sxA2, syA2, szA2, distA, qxA, qyA, qzA, tid, p0);
        if (lane == 0) sred[warp] = pkA;
        __syncthreads();                                 // bar1

        if (warp == 0) {
            // publish A[it] (coords from A slice); poll B[it-1] -> qB(it-1)
            sync_phase(sred, sbcB, histB, sxA, syA, szA,
                       bA, it, bB, it - 1, it > 1, c, p0, lane, c == 1);
        }
        __syncthreads();                                 // bar2
        if (it > 1) {
            float dmy;
            unpack2(qxB, qyB, sbcB[0]);
            unpack2(qzB, dmy, sbcB[1]);
        }

        // ---- phase B: compute B(it) with qB(it-1) ----
        unsigned long long pkB =
            compute_phase(sxB2, syB2, szB2, distB, qxB, qyB, qzB, tid, p0);
        if (lane == 0) sred[warp] = pkB;
        __syncthreads();                                 // bar3

        if (warp == 0) {
            // publish B[it] (coords from B slice); poll A[it] -> qA(it)
            sync_phase(sred, sbcA, histA, sxB, syB, szB,
                       bB, it, bA, it, true, c, p0, lane, c == 0);
        }
        __syncthreads();                                 // bar4
        {
            float dmy;
            unpack2(qxA, qyA, sbcA[0]);
            unpack2(qzA, dmy, sbcA[1]);
        }
    }

    // ---- epilogue: select B[KSEL-1] for history (c==1 records it) ----
    if (c == 1 && warp == 0) {
        unsigned long long pkj = 0, a0 = 1, a1, b0, b1 = 1;
        const unsigned long long* pent = &g_pub[bB][KSEL - 1][lane & 15][0];
        if (lane < CTAS_PER_B) {
            do {
                ld_b128_relaxed(a0, a1, &pent[0]);
                ld_b128_relaxed(b0, b1, &pent[2]);
            } while (a0 == 0ULL || b1 == 0ULL);
            pkj = a0;
        }
        unsigned long long m = pkj;
#pragma unroll
        for (int off = 8; off > 0; off >>= 1) {
            unsigned long long o = __shfl_xor_sync(0xffffffffu, m, off);
            if (o > m) m = o;
        }
        unsigned long long m0 = __shfl_sync(0xffffffffu, m, 0);
        if (lane == 0) histB[KSEL - 1] = ~(unsigned)(m0 & 0xffffffffULL);
    }
    __syncthreads();

    // ---- final output gather (off the critical path) ----
    if (c == 0) {
        for (int i = tid; i < (KSEL - 1) * NCH; i += THREADS) {
            int itr = i / NCH + 1, ch = i % NCH;
            out[((size_t)bA * KSEL + itr) * NCH + ch] =
                baseA[(size_t)histA[itr] * NCH + ch];
        }
    }
    if (c == 1) {
        for (int i = tid; i < (KSEL - 1) * NCH; i += THREADS) {
            int itr = i / NCH + 1, ch = i % NCH;
            out[((size_t)bB * KSEL + itr) * NCH + ch] =
                baseB[(size_t)histB[itr] * NCH + ch];
        }
    }
}

extern "C" void kernel_launch(void* const* d_in, const int* in_sizes, int n_in,
                              void* d_out, int out_size) {
    const float* pts = (const float*)d_in[0];
    float* out = (float*)d_out;

    static bool attr_set = false;
    if (!attr_set) {
        cudaFuncSetAttribute(fps_kernel,
                             cudaFuncAttributeMaxDynamicSharedMemorySize,
                             6 * NPC * sizeof(float));
        attr_set = true;
    }

    fps_init_kernel<<<256, 512>>>();
    fps_kernel<<<NPAIRS * CTAS_PER_B, THREADS, 6 * NPC * sizeof(float)>>>(pts, out);
}